// round 10
// baseline (speedup 1.0000x reference)
#include <cuda_runtime.h>
#include <math.h>
#include <stdint.h>

#define NODES   16384
#define EDGES   262144
#define DIM     256
#define NGRAPH  128
#define PERG    128
#define NLAYERS 5

// ---------------- scratch (device globals; no runtime allocation) ----------
__device__ float g_h   [NODES * DIM];
__device__ float g_e   [(size_t)EDGES * DIM];
__device__ float g_agg [NODES * DIM];
__device__ float g_t2  [NODES * DIM];
__device__ float g_t3  [NODES * DIM];
__device__ float g_qkv [NODES * 768];
__device__ float g_h1  [NODES * DIM];
__device__ int   g_deg [NODES];
__device__ int   g_off [NODES + 1];
__device__ int   g_cur [NODES];
__device__ int2  g_epair[EDGES];

// packed (hi/lo bf16 interleaved; word 2p = hi of k-pair p, 2p+1 = lo)
__device__ uint32_t pk_x   [NODES * 128];
__device__ uint32_t pk_ea  [(size_t)EDGES * 64];
__device__ uint32_t pk_nw  [256 * 128];
__device__ uint32_t pk_ew  [256 * 64];
__device__ uint32_t pk_w1  [NLAYERS * 256 * 256];
__device__ uint32_t pk_w2  [NLAYERS * 256 * 256];
__device__ uint32_t pk_inw [NLAYERS * 768 * 256];
__device__ uint32_t pk_onw [NLAYERS * 256 * 256];
__device__ uint32_t pk_mw1 [NLAYERS * 512 * 256];
__device__ uint32_t pk_mw2 [NLAYERS * 256 * 512];
__device__ uint32_t pk_agg [NODES * 256];
__device__ uint32_t pk_t1  [NODES * 512];
__device__ uint32_t pk_h   [NODES * 256];
__device__ uint32_t pk_attn[NODES * 256];

// ---------------- helpers ---------------------------------------------------
__device__ __forceinline__ void cvtstore(uint32_t* p, float4 v) {
    uint32_t h01, l01, h23, l23;
    asm("cvt.rn.bf16x2.f32 %0, %1, %2;" : "=r"(h01) : "f"(v.y), "f"(v.x));
    asm("cvt.rn.bf16x2.f32 %0, %1, %2;" : "=r"(h23) : "f"(v.w), "f"(v.z));
    float h0 = __uint_as_float(h01 << 16);
    float h1 = __uint_as_float(h01 & 0xffff0000u);
    float h2 = __uint_as_float(h23 << 16);
    float h3 = __uint_as_float(h23 & 0xffff0000u);
    asm("cvt.rn.bf16x2.f32 %0, %1, %2;" : "=r"(l01) : "f"(v.y - h1), "f"(v.x - h0));
    asm("cvt.rn.bf16x2.f32 %0, %1, %2;" : "=r"(l23) : "f"(v.w - h3), "f"(v.z - h2));
    *(uint4*)p = make_uint4(h01, l01, h23, l23);
}

__device__ __forceinline__ uint2 pack2(float v0, float v1) {
    uint32_t h01, l01;
    asm("cvt.rn.bf16x2.f32 %0, %1, %2;" : "=r"(h01) : "f"(v1), "f"(v0));
    float h0 = __uint_as_float(h01 << 16);
    float h1 = __uint_as_float(h01 & 0xffff0000u);
    asm("cvt.rn.bf16x2.f32 %0, %1, %2;" : "=r"(l01) : "f"(v1 - h1), "f"(v0 - h0));
    return make_uint2(h01, l01);
}

__device__ __forceinline__ uint32_t smem_u32(const void* p) {
    uint32_t a;
    asm("{ .reg .u64 t; cvta.to.shared.u64 t, %1; cvt.u32.u64 %0, t; }" : "=r"(a) : "l"(p));
    return a;
}

__device__ __forceinline__ void cp16(uint32_t s, const void* g) {
    asm volatile("cp.async.cg.shared.global [%0], [%1], 16;" :: "r"(s), "l"(g));
}
#define CP_COMMIT() asm volatile("cp.async.commit_group;")
#define CP_WAIT1()  asm volatile("cp.async.wait_group 1;")
#define CP_WAIT0()  asm volatile("cp.async.wait_group 0;")

// packed fp32x2 math (Blackwell base ISA)
__device__ __forceinline__ uint64_t fma2(uint64_t a, uint64_t b, uint64_t c) {
    uint64_t d;
    asm("fma.rn.f32x2 %0, %1, %2, %3;" : "=l"(d) : "l"(a), "l"(b), "l"(c));
    return d;
}
__device__ __forceinline__ uint64_t add2(uint64_t a, uint64_t b) {
    uint64_t d;
    asm("add.rn.f32x2 %0, %1, %2;" : "=l"(d) : "l"(a), "l"(b));
    return d;
}

// ---------------- pack: fp32 -> hi/lo bf16 interleaved ----------------------
__global__ void pack_kernel(const float* __restrict__ in, uint32_t* __restrict__ out, int n4)
{
    int i = blockIdx.x * blockDim.x + threadIdx.x;
    if (i < n4) {
        float4 v = ((const float4*)in)[i];
        cvtstore(out + (size_t)i * 4, v);
    }
}

// ============================================================================
// Tensor-core GEMM (3xBF16 split), pre-packed operands, cp.async 3-stage.
// ============================================================================
#define SROWW 24
#define STAGEW (256 * SROWW)

#define MMA_BF16(d, a0, a1, a2, a3, b0, b1)                                    \
    asm volatile(                                                              \
        "mma.sync.aligned.m16n8k16.row.col.f32.bf16.bf16.f32 "                 \
        "{%0,%1,%2,%3}, {%4,%5,%6,%7}, {%8,%9}, {%0,%1,%2,%3};"                \
        : "+f"(d[0]), "+f"(d[1]), "+f"(d[2]), "+f"(d[3])                       \
        : "r"(a0), "r"(a1), "r"(a2), "r"(a3), "r"(b0), "r"(b1))

__global__ void __launch_bounds__(256, 2)
gemm_tc(const uint32_t* __restrict__ A, const uint32_t* __restrict__ W,
        const float* __restrict__ bias, float* __restrict__ Cf,
        uint32_t* __restrict__ Cp, int M, int N, int K, int act)
{
    extern __shared__ uint32_t smem[];

    const int tid  = threadIdx.x;
    const int lane = tid & 31;
    const int wid  = tid >> 5;
    const int g  = lane >> 2;
    const int tg = lane & 3;
    const int warpM = wid & 1;
    const int warpN = wid >> 1;
    const int m0 = blockIdx.y << 7, n0 = blockIdx.x << 7;

    const int r0 = tid >> 2;
    const int kq = (tid & 3) << 2;

    const uint32_t* gA0 = A + (size_t)(m0 + r0)      * K + kq;
    const uint32_t* gA1 = A + (size_t)(m0 + r0 + 64) * K + kq;
    const uint32_t* gW0 = W + (size_t)(n0 + r0)      * K + kq;
    const uint32_t* gW1 = W + (size_t)(n0 + r0 + 64) * K + kq;

    const uint32_t sb = smem_u32(smem);
    const uint32_t stA = sb + (r0 * SROWW + kq) * 4;
    const uint32_t stW = stA + 128 * SROWW * 4;

    float acc[4][4][4];
#pragma unroll
    for (int i = 0; i < 4; i++)
#pragma unroll
        for (int j = 0; j < 4; j++)
#pragma unroll
            for (int c = 0; c < 4; c++) acc[i][j][c] = 0.f;

    const int KT = K >> 4;

    {
        cp16(stA, gA0); cp16(stA + 64 * SROWW * 4, gA1);
        cp16(stW, gW0); cp16(stW + 64 * SROWW * 4, gW1);
        CP_COMMIT();
        if (KT > 1) {
            uint32_t off = STAGEW * 4;
            cp16(stA + off, gA0 + 16); cp16(stA + off + 64 * SROWW * 4, gA1 + 16);
            cp16(stW + off, gW0 + 16); cp16(stW + off + 64 * SROWW * 4, gW1 + 16);
        }
        CP_COMMIT();
    }

    for (int kt = 0; kt < KT; kt++) {
        CP_WAIT1();
        __syncthreads();

        if (kt + 2 < KT) {
            const uint32_t off = (uint32_t)((kt + 2) % 3) * STAGEW * 4;
            const int ko = (kt + 2) << 4;
            cp16(stA + off, gA0 + ko); cp16(stA + off + 64 * SROWW * 4, gA1 + ko);
            cp16(stW + off, gW0 + ko); cp16(stW + off + 64 * SROWW * 4, gW1 + ko);
        }
        CP_COMMIT();

        const uint32_t* bA = smem + (kt % 3) * STAGEW + (warpM * 64) * SROWW;
        const uint32_t* bW = smem + (kt % 3) * STAGEW + 128 * SROWW + (warpN * 32) * SROWW;
        const int ko2 = tg * 2;

        uint32_t ah[4][4], al[4][4], bh[4][2], bl[4][2];
#pragma unroll
        for (int ni = 0; ni < 4; ni++) {
            const uint32_t* p = bW + (ni * 8 + g) * SROWW + ko2;
            uint2 z0 = *(const uint2*)(p);
            uint2 z1 = *(const uint2*)(p + 8);
            bh[ni][0] = z0.x; bl[ni][0] = z0.y;
            bh[ni][1] = z1.x; bl[ni][1] = z1.y;
        }
#pragma unroll
        for (int mi = 0; mi < 4; mi++) {
            const uint32_t* p = bA + (mi * 16 + g) * SROWW + ko2;
            uint2 x0 = *(const uint2*)(p);
            uint2 x1 = *(const uint2*)(p + 8 * SROWW);
            uint2 x2 = *(const uint2*)(p + 8);
            uint2 x3 = *(const uint2*)(p + 8 * SROWW + 8);
            ah[mi][0] = x0.x; al[mi][0] = x0.y;
            ah[mi][1] = x1.x; al[mi][1] = x1.y;
            ah[mi][2] = x2.x; al[mi][2] = x2.y;
            ah[mi][3] = x3.x; al[mi][3] = x3.y;
        }
#pragma unroll
        for (int mi = 0; mi < 4; mi++)
#pragma unroll
            for (int ni = 0; ni < 4; ni++) {
                MMA_BF16(acc[mi][ni], ah[mi][0], ah[mi][1], ah[mi][2], ah[mi][3],
                         bh[ni][0], bh[ni][1]);
                MMA_BF16(acc[mi][ni], ah[mi][0], ah[mi][1], ah[mi][2], ah[mi][3],
                         bl[ni][0], bl[ni][1]);
                MMA_BF16(acc[mi][ni], al[mi][0], al[mi][1], al[mi][2], al[mi][3],
                         bh[ni][0], bh[ni][1]);
            }
    }
    CP_WAIT0();

#pragma unroll
    for (int mi = 0; mi < 4; mi++) {
        const int row = m0 + warpM * 64 + mi * 16 + g;
#pragma unroll
        for (int ni = 0; ni < 4; ni++) {
            const int col = n0 + warpN * 32 + ni * 8 + tg * 2;
            float b0 = bias ? bias[col]     : 0.f;
            float b1 = bias ? bias[col + 1] : 0.f;
            float v0 = acc[mi][ni][0] + b0;
            float v1 = acc[mi][ni][1] + b1;
            float v2 = acc[mi][ni][2] + b0;
            float v3 = acc[mi][ni][3] + b1;
            if (act == 1) {
                v0 = 0.5f * v0 * (1.f + erff(v0 * 0.70710678118654752f));
                v1 = 0.5f * v1 * (1.f + erff(v1 * 0.70710678118654752f));
                v2 = 0.5f * v2 * (1.f + erff(v2 * 0.70710678118654752f));
                v3 = 0.5f * v3 * (1.f + erff(v3 * 0.70710678118654752f));
            } else if (act == 2) {
                v0 = fmaxf(v0, 0.f); v1 = fmaxf(v1, 0.f);
                v2 = fmaxf(v2, 0.f); v3 = fmaxf(v3, 0.f);
            }
            if (Cf) {
                *(float2*)(Cf + (size_t)row * N + col)       = make_float2(v0, v1);
                *(float2*)(Cf + (size_t)(row + 8) * N + col) = make_float2(v2, v3);
            }
            if (Cp) {
                *(uint2*)(Cp + (size_t)row * N + col)       = pack2(v0, v1);
                *(uint2*)(Cp + (size_t)(row + 8) * N + col) = pack2(v2, v3);
            }
        }
    }
}

#define GEMM_SMEM (3 * STAGEW * 4)   // 73728 B

// ---------------- CSR build (by dst) ---------------------------------------
__global__ void count_deg_kernel(const int* __restrict__ dst, int* __restrict__ deg)
{
    int i = blockIdx.x * blockDim.x + threadIdx.x;
    if (i < EDGES) atomicAdd(&deg[dst[i]], 1);
}

__global__ void scan_kernel(const int* __restrict__ deg, int* __restrict__ off)
{
    __shared__ int part[1024];
    int t = threadIdx.x;
    int base = t * 16;
    int local[16];
    int s = 0;
#pragma unroll
    for (int i = 0; i < 16; i++) { local[i] = deg[base + i]; s += local[i]; }
    part[t] = s;
    __syncthreads();
    for (int d = 1; d < 1024; d <<= 1) {
        int v = (t >= d) ? part[t - d] : 0;
        __syncthreads();
        part[t] += v;
        __syncthreads();
    }
    int run = part[t] - s;
#pragma unroll
    for (int i = 0; i < 16; i++) { off[base + i] = run; run += local[i]; }
    if (t == 1023) off[NODES] = part[1023];
}

__global__ void fill_kernel(const int* __restrict__ src, const int* __restrict__ dst,
                            const int* __restrict__ off, int* __restrict__ cur,
                            int2* __restrict__ epair)
{
    int i = blockIdx.x * blockDim.x + threadIdx.x;
    if (i < EDGES) {
        int d = dst[i];
        int p = atomicAdd(&cur[d], 1);
        epair[off[d] + p] = make_int2(src[i], i);
    }
}

// ---------------- GINE gather: packed agg = h[n] + sum relu(h[src]+e) ------
__global__ void gine_gather_kernel(const float* __restrict__ h, const float* __restrict__ e,
                                   const int2* __restrict__ epair,
                                   const int* __restrict__ off, uint32_t* __restrict__ aggp)
{
    int warp = (blockIdx.x * blockDim.x + threadIdx.x) >> 5;
    int lane = threadIdx.x & 31;
    if (warp >= NODES) return;
    const float4* hn = (const float4*)(h + (size_t)warp * DIM);
    float4 acc0 = hn[lane];
    float4 acc1 = hn[lane + 32];
    int beg = off[warp], end = off[warp + 1];
    for (int t = beg; t < end; t++) {
        int2 pr = __ldg(&epair[t]);
        const float4* hs = (const float4*)(h + (size_t)pr.x * DIM);
        const float4* es = (const float4*)(e + (size_t)pr.y * DIM);
        float4 a = hs[lane], b = es[lane];
        acc0.x += fmaxf(a.x + b.x, 0.f);
        acc0.y += fmaxf(a.y + b.y, 0.f);
        acc0.z += fmaxf(a.z + b.z, 0.f);
        acc0.w += fmaxf(a.w + b.w, 0.f);
        a = hs[lane + 32]; b = es[lane + 32];
        acc1.x += fmaxf(a.x + b.x, 0.f);
        acc1.y += fmaxf(a.y + b.y, 0.f);
        acc1.z += fmaxf(a.z + b.z, 0.f);
        acc1.w += fmaxf(a.w + b.w, 0.f);
    }
    cvtstore(aggp + (size_t)warp * DIM + lane * 4,        acc0);
    cvtstore(aggp + (size_t)warp * DIM + (lane + 32) * 4, acc1);
}

// ------- graph LayerNorm: single global read (tile staged in smem) ---------
#define GLN_SMEM (PERG * DIM * 4)   // 131072 B

__global__ void gln_kernel(const float* __restrict__ a, const float* __restrict__ b,
                           const float* __restrict__ post,
                           const float* __restrict__ gamma, const float* __restrict__ beta,
                           float* __restrict__ outf, uint32_t* __restrict__ outp,
                           float* __restrict__ pool)
{
    extern __shared__ float4 sv[];   // 8192 float4
    const int g = blockIdx.x, t = threadIdx.x;
    const size_t base4 = (size_t)g * (PERG * DIM / 4);
    const float4* a4 = (const float4*)a + base4;
    const float4* b4 = b ? (const float4*)b + base4 : nullptr;
    const float4* p4 = post ? (const float4*)post + base4 : nullptr;

    float s = 0.f, ss = 0.f;
#pragma unroll 4
    for (int j = 0; j < 32; j++) {
        int i = t + j * 256;
        float4 v = a4[i];
        if (b4) { float4 w = b4[i]; v.x += w.x; v.y += w.y; v.z += w.z; v.w += w.w; }
        sv[i] = v;
        s  += (v.x + v.y) + (v.z + v.w);
        ss += (v.x * v.x + v.y * v.y) + (v.z * v.z + v.w * v.w);
    }
    __shared__ float rs[8], rss[8];
    for (int o = 16; o; o >>= 1) {
        s  += __shfl_down_sync(0xffffffffu, s,  o);
        ss += __shfl_down_sync(0xffffffffu, ss, o);
    }
    int w = t >> 5;
    if ((t & 31) == 0) { rs[w] = s; rss[w] = ss; }
    __syncthreads();
    __shared__ float smu, srstd;
    if (t == 0) {
        float S = 0.f, SS = 0.f;
        for (int i = 0; i < 8; i++) { S += rs[i]; SS += rss[i]; }
        float mu  = S / (float)(PERG * DIM);
        float var = SS / (float)(PERG * DIM) - mu * mu;
        smu = mu;
        srstd = rsqrtf(var + 1e-5f);
    }
    __syncthreads();
    const float mu = smu, rstd = srstd;
    const float4 gm = ((const float4*)gamma)[t & 63];
    const float4 bt = ((const float4*)beta)[t & 63];
    float4 colsum = make_float4(0.f, 0.f, 0.f, 0.f);
    for (int j = 0; j < 32; j++) {
        int i = t + j * 256;
        float4 v = sv[i];
        float4 r;
        r.x = (v.x - mu) * rstd * gm.x + bt.x;
        r.y = (v.y - mu) * rstd * gm.y + bt.y;
        r.z = (v.z - mu) * rstd * gm.z + bt.z;
        r.w = (v.w - mu) * rstd * gm.w + bt.w;
        if (p4) { float4 q = p4[i]; r.x += q.x; r.y += q.y; r.z += q.z; r.w += q.w; }
        if (outf) ((float4*)outf)[base4 + i] = r;
        if (outp) cvtstore(outp + (base4 + i) * 4, r);
        colsum.x += r.x; colsum.y += r.y; colsum.z += r.z; colsum.w += r.w;
    }
    if (pool) {
        __syncthreads();            // sv no longer needed; reuse as reduction buf
        float4* red = sv;
        red[t] = colsum;
        __syncthreads();
        if (t < 64) {
            float4 s0 = red[t], s1 = red[t + 64], s2 = red[t + 128], s3 = red[t + 192];
            float4 tot;
            tot.x = (s0.x + s1.x) + (s2.x + s3.x);
            tot.y = (s0.y + s1.y) + (s2.y + s3.y);
            tot.z = (s0.z + s1.z) + (s2.z + s3.z);
            tot.w = (s0.w + s1.w) + (s2.w + s3.w);
            ((float4*)pool)[(size_t)g * 64 + t] = tot;
        }
    }
}

// ---------------- per-graph MHA: packed f32x2 FMA --------------------------
#define ATTN_SMEM (16384 * 4)

__global__ void __launch_bounds__(128, 3)
attn_kernel(const float* __restrict__ qkv, uint32_t* __restrict__ outp)
{
    extern __shared__ float sm[];
    float* Ks = sm;
    float* Vs = sm + 8192;
    const int b  = blockIdx.x >> 2;
    const int hh = blockIdx.x & 3;
    const int t  = threadIdx.x;
    const size_t gbase = (size_t)b * PERG;

    for (int i = t; i < PERG * 64; i += 128) {
        int r = i >> 6, d = i & 63;
        size_t row = (gbase + r) * 768;
        Ks[i] = qkv[row + 256 + hh * 64 + d];
        Vs[i] = qkv[row + 512 + hh * 64 + d];
    }
    uint64_t q2[32];
    {
        const uint64_t* qp = (const uint64_t*)(qkv + (gbase + t) * 768 + hh * 64);
#pragma unroll
        for (int i = 0; i < 32; i++) q2[i] = qp[i];
    }
    __syncthreads();

    float sum = 0.f;
    uint64_t ac[32];
#pragma unroll
    for (int i = 0; i < 32; i++) ac[i] = 0ull;

    for (int j = 0; j < 128; j++) {
        const uint64_t* kr = (const uint64_t*)(Ks + j * 64);
        uint64_t a0 = 0ull, a1 = 0ull, a2 = 0ull, a3 = 0ull;
#pragma unroll
        for (int i = 0; i < 32; i += 4) {
            a0 = fma2(q2[i],     kr[i],     a0);
            a1 = fma2(q2[i + 1], kr[i + 1], a1);
            a2 = fma2(q2[i + 2], kr[i + 2], a2);
            a3 = fma2(q2[i + 3], kr[i + 3], a3);
        }
        a0 = add2(a0, a1);
        a2 = add2(a2, a3);
        a0 = add2(a0, a2);
        float lo = __uint_as_float((uint32_t)a0);
        float hi = __uint_as_float((uint32_t)(a0 >> 32));
        float p = __expf((lo + hi) * 0.125f);
        sum += p;
        uint64_t p2 = ((uint64_t)__float_as_uint(p) << 32) | __float_as_uint(p);
        const uint64_t* vr = (const uint64_t*)(Vs + j * 64);
#pragma unroll
        for (int i = 0; i < 32; i++)
            ac[i] = fma2(p2, vr[i], ac[i]);
    }
    const float inv = 1.f / sum;
    uint32_t* op = outp + (gbase + t) * DIM + hh * 64;
#pragma unroll
    for (int i = 0; i < 16; i++) {
        float4 v;
        v.x = __uint_as_float((uint32_t)ac[2 * i])            * inv;
        v.y = __uint_as_float((uint32_t)(ac[2 * i] >> 32))     * inv;
        v.z = __uint_as_float((uint32_t)ac[2 * i + 1])         * inv;
        v.w = __uint_as_float((uint32_t)(ac[2 * i + 1] >> 32)) * inv;
        cvtstore(op + i * 4, v);
    }
}

// ---------------- launch ------------------------------------------------------
extern "C" void kernel_launch(void* const* d_in, const int* in_sizes, int n_in,
                              void* d_out, int out_size)
{
    const float* x          = (const float*)d_in[0];
    const float* edge_attr  = (const float*)d_in[1];
    const int*   edge_index = (const int*)  d_in[2];
    const float* node_w     = (const float*)d_in[4];
    const float* edge_w     = (const float*)d_in[5];
    const float* conv_w1    = (const float*)d_in[6];
    const float* conv_b1    = (const float*)d_in[7];
    const float* conv_w2    = (const float*)d_in[8];
    const float* conv_b2    = (const float*)d_in[9];
    const float* attn_in_w  = (const float*)d_in[10];
    const float* attn_in_b  = (const float*)d_in[11];
    const float* attn_out_w = (const float*)d_in[12];
    const float* attn_out_b = (const float*)d_in[13];
    const float* n1_g       = (const float*)d_in[14];
    const float* n1_b       = (const float*)d_in[15];
    const float* n2_g       = (const float*)d_in[16];
    const float* n2_b       = (const float*)d_in[17];
    const float* n3_g       = (const float*)d_in[18];
    const float* n3_b       = (const float*)d_in[19];
    const float* mlp_w1     = (const float*)d_in[20];
    const float* mlp_b1     = (const float*)d_in[21];
    const float* mlp_w2     = (const float*)d_in[22];
    const float* mlp_b2     = (const float*)d_in[23];
    float* out = (float*)d_out;

    const int* src = edge_index;
    const int* dst = edge_index + EDGES;

    float *h_, *e_, *agg_, *t2_, *t3_, *qkv_, *h1_;
    int *deg_, *off_, *cur_;
    int2* epair_;
    uint32_t *pkx_, *pkea_, *pknw_, *pkew_, *pkw1_, *pkw2_, *pkinw_, *pkonw_,
             *pkmw1_, *pkmw2_, *pkagg_, *pkt1_, *pkh_, *pkattn_;
    cudaGetSymbolAddress((void**)&h_,    g_h);
    cudaGetSymbolAddress((void**)&e_,    g_e);
    cudaGetSymbolAddress((void**)&agg_,  g_agg);
    cudaGetSymbolAddress((void**)&t2_,   g_t2);
    cudaGetSymbolAddress((void**)&t3_,   g_t3);
    cudaGetSymbolAddress((void**)&qkv_,  g_qkv);
    cudaGetSymbolAddress((void**)&h1_,   g_h1);
    cudaGetSymbolAddress((void**)&deg_,  g_deg);
    cudaGetSymbolAddress((void**)&off_,  g_off);
    cudaGetSymbolAddress((void**)&cur_,  g_cur);
    cudaGetSymbolAddress((void**)&epair_,g_epair);
    cudaGetSymbolAddress((void**)&pkx_,   pk_x);
    cudaGetSymbolAddress((void**)&pkea_,  pk_ea);
    cudaGetSymbolAddress((void**)&pknw_,  pk_nw);
    cudaGetSymbolAddress((void**)&pkew_,  pk_ew);
    cudaGetSymbolAddress((void**)&pkw1_,  pk_w1);
    cudaGetSymbolAddress((void**)&pkw2_,  pk_w2);
    cudaGetSymbolAddress((void**)&pkinw_, pk_inw);
    cudaGetSymbolAddress((void**)&pkonw_, pk_onw);
    cudaGetSymbolAddress((void**)&pkmw1_, pk_mw1);
    cudaGetSymbolAddress((void**)&pkmw2_, pk_mw2);
    cudaGetSymbolAddress((void**)&pkagg_, pk_agg);
    cudaGetSymbolAddress((void**)&pkt1_,  pk_t1);
    cudaGetSymbolAddress((void**)&pkh_,   pk_h);
    cudaGetSymbolAddress((void**)&pkattn_,pk_attn);

    cudaFuncSetAttribute(attn_kernel, cudaFuncAttributeMaxDynamicSharedMemorySize, ATTN_SMEM);
    cudaFuncSetAttribute(gemm_tc,     cudaFuncAttributeMaxDynamicSharedMemorySize, GEMM_SMEM);
    cudaFuncSetAttribute(gln_kernel,  cudaFuncAttributeMaxDynamicSharedMemorySize, GLN_SMEM);

    cudaStream_t s2;
    cudaStreamCreateWithFlags(&s2, cudaStreamNonBlocking);
    cudaEvent_t evA, evB;
    cudaEventCreateWithFlags(&evA, cudaEventDisableTiming);
    cudaEventCreateWithFlags(&evB, cudaEventDisableTiming);

    // launches 0-2 = packs, launch 3 = node-embed GEMM (ncu capture window)
    pack_kernel<<<NODES * 128 / 1024, 256>>>(x, pkx_, NODES * 128 / 4);
    pack_kernel<<<32, 256>>>(node_w, pknw_, 256 * 128 / 4);
    pack_kernel<<<16, 256>>>(edge_w, pkew_, 256 * 64 / 4);
    gemm_tc<<<dim3(2, NODES / 128), 256, GEMM_SMEM>>>(pkx_, pknw_, nullptr, h_, pkh_, NODES, 256, 128, 0);

    pack_kernel<<<(int)((size_t)EDGES * 64 / 1024), 256>>>(edge_attr, pkea_, EDGES * 64 / 4);
    gemm_tc<<<dim3(2, EDGES / 128), 256, GEMM_SMEM>>>(pkea_, pkew_, nullptr, e_, nullptr, EDGES, 256, 64, 0);

    pack_kernel<<<NLAYERS * 256 * 256 / 1024, 256>>>(conv_w1, pkw1_, NLAYERS * 256 * 256 / 4);
    pack_kernel<<<NLAYERS * 256 * 256 / 1024, 256>>>(conv_w2, pkw2_, NLAYERS * 256 * 256 / 4);
    pack_kernel<<<NLAYERS * 768 * 256 / 1024, 256>>>(attn_in_w, pkinw_, NLAYERS * 768 * 256 / 4);
    pack_kernel<<<NLAYERS * 256 * 256 / 1024, 256>>>(attn_out_w, pkonw_, NLAYERS * 256 * 256 / 4);
    pack_kernel<<<NLAYERS * 512 * 256 / 1024, 256>>>(mlp_w1, pkmw1_, NLAYERS * 512 * 256 / 4);
    pack_kernel<<<NLAYERS * 256 * 512 / 1024, 256>>>(mlp_w2, pkmw2_, NLAYERS * 256 * 512 / 4);

    // CSR build
    cudaMemsetAsync(deg_, 0, NODES * sizeof(int));
    cudaMemsetAsync(cur_, 0, NODES * sizeof(int));
    count_deg_kernel<<<EDGES / 256, 256>>>(dst, deg_);
    scan_kernel<<<1, 1024>>>(deg_, off_);
    fill_kernel<<<EDGES / 256, 256>>>(src, dst, off_, cur_, epair_);

    for (int l = 0; l < NLAYERS; l++) {
        const uint32_t* w1  = pkw1_  + (size_t)l * 256 * 256;
        const uint32_t* w2  = pkw2_  + (size_t)l * 256 * 256;
        const uint32_t* inw = pkinw_ + (size_t)l * 768 * 256;
        const uint32_t* onw = pkonw_ + (size_t)l * 256 * 256;
        const uint32_t* mw1 = pkmw1_ + (size_t)l * 512 * 256;
        const uint32_t* mw2 = pkmw2_ + (size_t)l * 256 * 512;
        const float* b1  = conv_b1    + (size_t)l * DIM;
        const float* b2  = conv_b2    + (size_t)l * DIM;
        const float* inb = attn_in_b  + (size_t)l * 768;
        const float* onb = attn_out_b + (size_t)l * DIM;
        const float* mb1 = mlp_b1     + (size_t)l * 512;
        const float* mb2 = mlp_b2     + (size_t)l * DIM;

        // fork: attention chain on s2
        cudaEventRecord(evA, 0);
        cudaStreamWaitEvent(s2, evA, 0);
        gemm_tc<<<dim3(6, 128), 256, GEMM_SMEM, s2>>>(pkh_, inw, inb, qkv_, nullptr, NODES, 768, 256, 0);
        attn_kernel<<<NGRAPH * 4, 128, ATTN_SMEM, s2>>>(qkv_, pkattn_);
        gemm_tc<<<dim3(2, 128), 256, GEMM_SMEM, s2>>>(pkattn_, onw, onb, t3_, nullptr, NODES, 256, 256, 0);
        cudaEventRecord(evB, s2);

        // local chain on default stream
        gine_gather_kernel<<<NODES / 8, 256>>>(h_, e_, epair_, off_, pkagg_);
        gemm_tc<<<dim3(2, 128), 256, GEMM_SMEM>>>(pkagg_, w1, b1, nullptr, pkt1_, NODES, 256, 256, 1);
        gemm_tc<<<dim3(2, 128), 256, GEMM_SMEM>>>(pkt1_,  w2, b2, t2_, nullptr, NODES, 256, 256, 0);
        gln_kernel<<<NGRAPH, 256, GLN_SMEM>>>(t2_, h_, nullptr, n1_g + l * DIM, n1_b + l * DIM,
                                              h1_, nullptr, nullptr);

        // join
        cudaStreamWaitEvent(0, evB, 0);
        gln_kernel<<<NGRAPH, 256, GLN_SMEM>>>(t3_, h_, h1_, n2_g + l * DIM, n2_b + l * DIM,
                                              agg_, pkagg_, nullptr);
        gemm_tc<<<dim3(4, 128), 256, GEMM_SMEM>>>(pkagg_, mw1, mb1, nullptr, pkt1_, NODES, 512, 256, 2);
        gemm_tc<<<dim3(2, 128), 256, GEMM_SMEM>>>(pkt1_,  mw2, mb2, t2_, nullptr, NODES, 256, 512, 0);
        if (l == NLAYERS - 1) {
            gln_kernel<<<NGRAPH, 256, GLN_SMEM>>>(t2_, agg_, nullptr, n3_g + l * DIM, n3_b + l * DIM,
                                                  out, nullptr, out + (size_t)NODES * DIM);
        } else {
            gln_kernel<<<NGRAPH, 256, GLN_SMEM>>>(t2_, agg_, nullptr, n3_g + l * DIM, n3_b + l * DIM,
                                                  h_, pkh_, nullptr);
        }
    }
}

// round 11
// speedup vs baseline: 1.0498x; 1.0498x over previous
#include <cuda_runtime.h>
#include <math.h>
#include <stdint.h>

#define NODES   16384
#define EDGES   262144
#define DIM     256
#define NGRAPH  128
#define PERG    128
#define NLAYERS 5

// ---------------- scratch (device globals; no runtime allocation) ----------
__device__ float g_h   [NODES * DIM];
__device__ uint32_t g_ebf[(size_t)EDGES * 128];   // e in bf16 pairs (134MB)
__device__ float g_agg [NODES * DIM];
__device__ float g_t2  [NODES * DIM];
__device__ float g_t3  [NODES * DIM];
__device__ float g_qkv [NODES * 768];
__device__ float g_h1  [NODES * DIM];
__device__ int   g_deg [NODES];
__device__ int   g_off [NODES + 1];
__device__ int   g_cur [NODES];
__device__ int2  g_epair[EDGES];

// packed (hi/lo bf16 interleaved; word 2p = hi of k-pair p, 2p+1 = lo)
__device__ uint32_t pk_x   [NODES * 128];
__device__ uint32_t pk_ea  [(size_t)EDGES * 64];
__device__ uint32_t pk_nw  [256 * 128];
__device__ uint32_t pk_ew  [256 * 64];
__device__ uint32_t pk_w1  [NLAYERS * 256 * 256];
__device__ uint32_t pk_w2  [NLAYERS * 256 * 256];
__device__ uint32_t pk_inw [NLAYERS * 768 * 256];
__device__ uint32_t pk_onw [NLAYERS * 256 * 256];
__device__ uint32_t pk_mw1 [NLAYERS * 512 * 256];
__device__ uint32_t pk_mw2 [NLAYERS * 256 * 512];
__device__ uint32_t pk_agg [NODES * 256];
__device__ uint32_t pk_t1  [NODES * 512];
__device__ uint32_t pk_h   [NODES * 256];
__device__ uint32_t pk_attn[NODES * 256];

// ---------------- helpers ---------------------------------------------------
__device__ __forceinline__ void cvtstore(uint32_t* p, float4 v) {
    uint32_t h01, l01, h23, l23;
    asm("cvt.rn.bf16x2.f32 %0, %1, %2;" : "=r"(h01) : "f"(v.y), "f"(v.x));
    asm("cvt.rn.bf16x2.f32 %0, %1, %2;" : "=r"(h23) : "f"(v.w), "f"(v.z));
    float h0 = __uint_as_float(h01 << 16);
    float h1 = __uint_as_float(h01 & 0xffff0000u);
    float h2 = __uint_as_float(h23 << 16);
    float h3 = __uint_as_float(h23 & 0xffff0000u);
    asm("cvt.rn.bf16x2.f32 %0, %1, %2;" : "=r"(l01) : "f"(v.y - h1), "f"(v.x - h0));
    asm("cvt.rn.bf16x2.f32 %0, %1, %2;" : "=r"(l23) : "f"(v.w - h3), "f"(v.z - h2));
    *(uint4*)p = make_uint4(h01, l01, h23, l23);
}

__device__ __forceinline__ uint2 pack2(float v0, float v1) {
    uint32_t h01, l01;
    asm("cvt.rn.bf16x2.f32 %0, %1, %2;" : "=r"(h01) : "f"(v1), "f"(v0));
    float h0 = __uint_as_float(h01 << 16);
    float h1 = __uint_as_float(h01 & 0xffff0000u);
    asm("cvt.rn.bf16x2.f32 %0, %1, %2;" : "=r"(l01) : "f"(v1 - h1), "f"(v0 - h0));
    return make_uint2(h01, l01);
}

__device__ __forceinline__ uint32_t bfpair(float v0, float v1) {
    uint32_t h;
    asm("cvt.rn.bf16x2.f32 %0, %1, %2;" : "=r"(h) : "f"(v1), "f"(v0));
    return h;   // low = v0, high = v1
}

__device__ __forceinline__ uint32_t smem_u32(const void* p) {
    uint32_t a;
    asm("{ .reg .u64 t; cvta.to.shared.u64 t, %1; cvt.u32.u64 %0, t; }" : "=r"(a) : "l"(p));
    return a;
}

__device__ __forceinline__ void cp16(uint32_t s, const void* g) {
    asm volatile("cp.async.cg.shared.global [%0], [%1], 16;" :: "r"(s), "l"(g));
}
#define CP_COMMIT() asm volatile("cp.async.commit_group;")
#define CP_WAIT1()  asm volatile("cp.async.wait_group 1;")
#define CP_WAIT0()  asm volatile("cp.async.wait_group 0;")

// packed fp32x2 math (Blackwell base ISA)
__device__ __forceinline__ uint64_t fma2(uint64_t a, uint64_t b, uint64_t c) {
    uint64_t d;
    asm("fma.rn.f32x2 %0, %1, %2, %3;" : "=l"(d) : "l"(a), "l"(b), "l"(c));
    return d;
}
__device__ __forceinline__ uint64_t add2(uint64_t a, uint64_t b) {
    uint64_t d;
    asm("add.rn.f32x2 %0, %1, %2;" : "=l"(d) : "l"(a), "l"(b));
    return d;
}

// ---------------- pack: fp32 -> hi/lo bf16 interleaved ----------------------
__global__ void pack_kernel(const float* __restrict__ in, uint32_t* __restrict__ out, int n4)
{
    int i = blockIdx.x * blockDim.x + threadIdx.x;
    if (i < n4) {
        float4 v = ((const float4*)in)[i];
        cvtstore(out + (size_t)i * 4, v);
    }
}

// ============================================================================
// Tensor-core GEMM (3xBF16 split), pre-packed operands, cp.async 3-stage.
// Outputs: Cf (fp32), Cp (packed hi/lo), Cb (plain bf16 pairs) — any subset.
// ============================================================================
#define SROWW 24
#define STAGEW (256 * SROWW)

#define MMA_BF16(d, a0, a1, a2, a3, b0, b1)                                    \
    asm volatile(                                                              \
        "mma.sync.aligned.m16n8k16.row.col.f32.bf16.bf16.f32 "                 \
        "{%0,%1,%2,%3}, {%4,%5,%6,%7}, {%8,%9}, {%0,%1,%2,%3};"                \
        : "+f"(d[0]), "+f"(d[1]), "+f"(d[2]), "+f"(d[3])                       \
        : "r"(a0), "r"(a1), "r"(a2), "r"(a3), "r"(b0), "r"(b1))

__global__ void __launch_bounds__(256, 2)
gemm_tc(const uint32_t* __restrict__ A, const uint32_t* __restrict__ W,
        const float* __restrict__ bias, float* __restrict__ Cf,
        uint32_t* __restrict__ Cp, uint32_t* __restrict__ Cb,
        int M, int N, int K, int act)
{
    extern __shared__ uint32_t smem[];

    const int tid  = threadIdx.x;
    const int lane = tid & 31;
    const int wid  = tid >> 5;
    const int g  = lane >> 2;
    const int tg = lane & 3;
    const int warpM = wid & 1;
    const int warpN = wid >> 1;
    const int m0 = blockIdx.y << 7, n0 = blockIdx.x << 7;

    const int r0 = tid >> 2;
    const int kq = (tid & 3) << 2;

    const uint32_t* gA0 = A + (size_t)(m0 + r0)      * K + kq;
    const uint32_t* gA1 = A + (size_t)(m0 + r0 + 64) * K + kq;
    const uint32_t* gW0 = W + (size_t)(n0 + r0)      * K + kq;
    const uint32_t* gW1 = W + (size_t)(n0 + r0 + 64) * K + kq;

    const uint32_t sb = smem_u32(smem);
    const uint32_t stA = sb + (r0 * SROWW + kq) * 4;
    const uint32_t stW = stA + 128 * SROWW * 4;

    float acc[4][4][4];
#pragma unroll
    for (int i = 0; i < 4; i++)
#pragma unroll
        for (int j = 0; j < 4; j++)
#pragma unroll
            for (int c = 0; c < 4; c++) acc[i][j][c] = 0.f;

    const int KT = K >> 4;

    {
        cp16(stA, gA0); cp16(stA + 64 * SROWW * 4, gA1);
        cp16(stW, gW0); cp16(stW + 64 * SROWW * 4, gW1);
        CP_COMMIT();
        if (KT > 1) {
            uint32_t off = STAGEW * 4;
            cp16(stA + off, gA0 + 16); cp16(stA + off + 64 * SROWW * 4, gA1 + 16);
            cp16(stW + off, gW0 + 16); cp16(stW + off + 64 * SROWW * 4, gW1 + 16);
        }
        CP_COMMIT();
    }

    for (int kt = 0; kt < KT; kt++) {
        CP_WAIT1();
        __syncthreads();

        if (kt + 2 < KT) {
            const uint32_t off = (uint32_t)((kt + 2) % 3) * STAGEW * 4;
            const int ko = (kt + 2) << 4;
            cp16(stA + off, gA0 + ko); cp16(stA + off + 64 * SROWW * 4, gA1 + ko);
            cp16(stW + off, gW0 + ko); cp16(stW + off + 64 * SROWW * 4, gW1 + ko);
        }
        CP_COMMIT();

        const uint32_t* bA = smem + (kt % 3) * STAGEW + (warpM * 64) * SROWW;
        const uint32_t* bW = smem + (kt % 3) * STAGEW + 128 * SROWW + (warpN * 32) * SROWW;
        const int ko2 = tg * 2;

        uint32_t ah[4][4], al[4][4], bh[4][2], bl[4][2];
#pragma unroll
        for (int ni = 0; ni < 4; ni++) {
            const uint32_t* p = bW + (ni * 8 + g) * SROWW + ko2;
            uint2 z0 = *(const uint2*)(p);
            uint2 z1 = *(const uint2*)(p + 8);
            bh[ni][0] = z0.x; bl[ni][0] = z0.y;
            bh[ni][1] = z1.x; bl[ni][1] = z1.y;
        }
#pragma unroll
        for (int mi = 0; mi < 4; mi++) {
            const uint32_t* p = bA + (mi * 16 + g) * SROWW + ko2;
            uint2 x0 = *(const uint2*)(p);
            uint2 x1 = *(const uint2*)(p + 8 * SROWW);
            uint2 x2 = *(const uint2*)(p + 8);
            uint2 x3 = *(const uint2*)(p + 8 * SROWW + 8);
            ah[mi][0] = x0.x; al[mi][0] = x0.y;
            ah[mi][1] = x1.x; al[mi][1] = x1.y;
            ah[mi][2] = x2.x; al[mi][2] = x2.y;
            ah[mi][3] = x3.x; al[mi][3] = x3.y;
        }
#pragma unroll
        for (int mi = 0; mi < 4; mi++)
#pragma unroll
            for (int ni = 0; ni < 4; ni++) {
                MMA_BF16(acc[mi][ni], ah[mi][0], ah[mi][1], ah[mi][2], ah[mi][3],
                         bh[ni][0], bh[ni][1]);
                MMA_BF16(acc[mi][ni], ah[mi][0], ah[mi][1], ah[mi][2], ah[mi][3],
                         bl[ni][0], bl[ni][1]);
                MMA_BF16(acc[mi][ni], al[mi][0], al[mi][1], al[mi][2], al[mi][3],
                         bh[ni][0], bh[ni][1]);
            }
    }
    CP_WAIT0();

#pragma unroll
    for (int mi = 0; mi < 4; mi++) {
        const int row = m0 + warpM * 64 + mi * 16 + g;
#pragma unroll
        for (int ni = 0; ni < 4; ni++) {
            const int col = n0 + warpN * 32 + ni * 8 + tg * 2;
            float b0 = bias ? bias[col]     : 0.f;
            float b1 = bias ? bias[col + 1] : 0.f;
            float v0 = acc[mi][ni][0] + b0;
            float v1 = acc[mi][ni][1] + b1;
            float v2 = acc[mi][ni][2] + b0;
            float v3 = acc[mi][ni][3] + b1;
            if (act == 1) {
                v0 = 0.5f * v0 * (1.f + erff(v0 * 0.70710678118654752f));
                v1 = 0.5f * v1 * (1.f + erff(v1 * 0.70710678118654752f));
                v2 = 0.5f * v2 * (1.f + erff(v2 * 0.70710678118654752f));
                v3 = 0.5f * v3 * (1.f + erff(v3 * 0.70710678118654752f));
            } else if (act == 2) {
                v0 = fmaxf(v0, 0.f); v1 = fmaxf(v1, 0.f);
                v2 = fmaxf(v2, 0.f); v3 = fmaxf(v3, 0.f);
            }
            if (Cf) {
                *(float2*)(Cf + (size_t)row * N + col)       = make_float2(v0, v1);
                *(float2*)(Cf + (size_t)(row + 8) * N + col) = make_float2(v2, v3);
            }
            if (Cp) {
                *(uint2*)(Cp + (size_t)row * N + col)       = pack2(v0, v1);
                *(uint2*)(Cp + (size_t)(row + 8) * N + col) = pack2(v2, v3);
            }
            if (Cb) {
                Cb[((size_t)row * N + col) >> 1]       = bfpair(v0, v1);
                Cb[((size_t)(row + 8) * N + col) >> 1] = bfpair(v2, v3);
            }
        }
    }
}

#define GEMM_SMEM (3 * STAGEW * 4)   // 73728 B

// ---------------- CSR build (by dst) ---------------------------------------
__global__ void count_deg_kernel(const int* __restrict__ dst, int* __restrict__ deg)
{
    int i = blockIdx.x * blockDim.x + threadIdx.x;
    if (i < EDGES) atomicAdd(&deg[dst[i]], 1);
}

__global__ void scan_kernel(const int* __restrict__ deg, int* __restrict__ off)
{
    __shared__ int part[1024];
    int t = threadIdx.x;
    int base = t * 16;
    int local[16];
    int s = 0;
#pragma unroll
    for (int i = 0; i < 16; i++) { local[i] = deg[base + i]; s += local[i]; }
    part[t] = s;
    __syncthreads();
    for (int d = 1; d < 1024; d <<= 1) {
        int v = (t >= d) ? part[t - d] : 0;
        __syncthreads();
        part[t] += v;
        __syncthreads();
    }
    int run = part[t] - s;
#pragma unroll
    for (int i = 0; i < 16; i++) { off[base + i] = run; run += local[i]; }
    if (t == 1023) off[NODES] = part[1023];
}

__global__ void fill_kernel(const int* __restrict__ src, const int* __restrict__ dst,
                            const int* __restrict__ off, int* __restrict__ cur,
                            int2* __restrict__ epair)
{
    int i = blockIdx.x * blockDim.x + threadIdx.x;
    if (i < EDGES) {
        int d = dst[i];
        int p = atomicAdd(&cur[d], 1);
        epair[off[d] + p] = make_int2(src[i], i);
    }
}

// ---------------- GINE gather: packed agg = h[n] + sum relu(h[src]+e) ------
// e in bf16 pairs: lane reads uint2 (4 values) per row half.
__global__ void gine_gather_kernel(const float* __restrict__ h, const uint32_t* __restrict__ ebf,
                                   const int2* __restrict__ epair,
                                   const int* __restrict__ off, uint32_t* __restrict__ aggp)
{
    int warp = (blockIdx.x * blockDim.x + threadIdx.x) >> 5;
    int lane = threadIdx.x & 31;
    if (warp >= NODES) return;
    const float4* hn = (const float4*)(h + (size_t)warp * DIM);
    float4 acc0 = hn[lane];
    float4 acc1 = hn[lane + 32];
    int beg = off[warp], end = off[warp + 1];
    for (int t = beg; t < end; t++) {
        int2 pr = __ldg(&epair[t]);
        const float4* hs = (const float4*)(h + (size_t)pr.x * DIM);
        const uint2* er  = (const uint2*)(ebf + (size_t)pr.y * 128);
        float4 a = hs[lane];
        uint2 w = __ldg(&er[lane]);
        acc0.x += fmaxf(a.x + __uint_as_float(w.x << 16),          0.f);
        acc0.y += fmaxf(a.y + __uint_as_float(w.x & 0xffff0000u),  0.f);
        acc0.z += fmaxf(a.z + __uint_as_float(w.y << 16),          0.f);
        acc0.w += fmaxf(a.w + __uint_as_float(w.y & 0xffff0000u),  0.f);
        a = hs[lane + 32];
        w = __ldg(&er[lane + 32]);
        acc1.x += fmaxf(a.x + __uint_as_float(w.x << 16),          0.f);
        acc1.y += fmaxf(a.y + __uint_as_float(w.x & 0xffff0000u),  0.f);
        acc1.z += fmaxf(a.z + __uint_as_float(w.y << 16),          0.f);
        acc1.w += fmaxf(a.w + __uint_as_float(w.y & 0xffff0000u),  0.f);
    }
    cvtstore(aggp + (size_t)warp * DIM + lane * 4,        acc0);
    cvtstore(aggp + (size_t)warp * DIM + (lane + 32) * 4, acc1);
}

// ------- graph LayerNorm (round-9 form): dual out + optional fused pool ----
__global__ void gln_kernel(const float* __restrict__ a, const float* __restrict__ b,
                           const float* __restrict__ post,
                           const float* __restrict__ gamma, const float* __restrict__ beta,
                           float* __restrict__ outf, uint32_t* __restrict__ outp,
                           float* __restrict__ pool)
{
    const int g = blockIdx.x, t = threadIdx.x;
    const size_t base4 = (size_t)g * (PERG * DIM / 4);
    const float4* a4 = (const float4*)a + base4;
    const float4* b4 = b ? (const float4*)b + base4 : nullptr;
    const float4* p4 = post ? (const float4*)post + base4 : nullptr;

    float s = 0.f, ss = 0.f;
#pragma unroll 4
    for (int j = 0; j < 32; j++) {
        int i = t + j * 256;
        float4 v = a4[i];
        if (b4) { float4 w = b4[i]; v.x += w.x; v.y += w.y; v.z += w.z; v.w += w.w; }
        s  += (v.x + v.y) + (v.z + v.w);
        ss += (v.x * v.x + v.y * v.y) + (v.z * v.z + v.w * v.w);
    }
    __shared__ float rs[8], rss[8];
    for (int o = 16; o; o >>= 1) {
        s  += __shfl_down_sync(0xffffffffu, s,  o);
        ss += __shfl_down_sync(0xffffffffu, ss, o);
    }
    int w = t >> 5;
    if ((t & 31) == 0) { rs[w] = s; rss[w] = ss; }
    __syncthreads();
    __shared__ float smu, srstd;
    if (t == 0) {
        float S = 0.f, SS = 0.f;
        for (int i = 0; i < 8; i++) { S += rs[i]; SS += rss[i]; }
        float mu  = S / (float)(PERG * DIM);
        float var = SS / (float)(PERG * DIM) - mu * mu;
        smu = mu;
        srstd = rsqrtf(var + 1e-5f);
    }
    __syncthreads();
    const float mu = smu, rstd = srstd;
    const float4 gm = ((const float4*)gamma)[t & 63];
    const float4 bt = ((const float4*)beta)[t & 63];
    float4 colsum = make_float4(0.f, 0.f, 0.f, 0.f);
    for (int j = 0; j < 32; j++) {
        int i = t + j * 256;
        float4 v = a4[i];
        if (b4) { float4 x = b4[i]; v.x += x.x; v.y += x.y; v.z += x.z; v.w += x.w; }
        float4 r;
        r.x = (v.x - mu) * rstd * gm.x + bt.x;
        r.y = (v.y - mu) * rstd * gm.y + bt.y;
        r.z = (v.z - mu) * rstd * gm.z + bt.z;
        r.w = (v.w - mu) * rstd * gm.w + bt.w;
        if (p4) { float4 q = p4[i]; r.x += q.x; r.y += q.y; r.z += q.z; r.w += q.w; }
        if (outf) ((float4*)outf)[base4 + i] = r;
        if (outp) cvtstore(outp + (base4 + i) * 4, r);
        colsum.x += r.x; colsum.y += r.y; colsum.z += r.z; colsum.w += r.w;
    }
    if (pool) {
        __shared__ float4 red[256];
        red[t] = colsum;
        __syncthreads();
        if (t < 64) {
            float4 s0 = red[t], s1 = red[t + 64], s2 = red[t + 128], s3 = red[t + 192];
            float4 tot;
            tot.x = (s0.x + s1.x) + (s2.x + s3.x);
            tot.y = (s0.y + s1.y) + (s2.y + s3.y);
            tot.z = (s0.z + s1.z) + (s2.z + s3.z);
            tot.w = (s0.w + s1.w) + (s2.w + s3.w);
            ((float4*)pool)[(size_t)g * 64 + t] = tot;
        }
    }
}

// ---------------- per-graph MHA: packed f32x2 FMA --------------------------
#define ATTN_SMEM (16384 * 4)

__global__ void __launch_bounds__(128, 3)
attn_kernel(const float* __restrict__ qkv, uint32_t* __restrict__ outp)
{
    extern __shared__ float sm[];
    float* Ks = sm;
    float* Vs = sm + 8192;
    const int b  = blockIdx.x >> 2;
    const int hh = blockIdx.x & 3;
    const int t  = threadIdx.x;
    const size_t gbase = (size_t)b * PERG;

    for (int i = t; i < PERG * 64; i += 128) {
        int r = i >> 6, d = i & 63;
        size_t row = (gbase + r) * 768;
        Ks[i] = qkv[row + 256 + hh * 64 + d];
        Vs[i] = qkv[row + 512 + hh * 64 + d];
    }
    uint64_t q2[32];
    {
        const uint64_t* qp = (const uint64_t*)(qkv + (gbase + t) * 768 + hh * 64);
#pragma unroll
        for (int i = 0; i < 32; i++) q2[i] = qp[i];
    }
    __syncthreads();

    float sum = 0.f;
    uint64_t ac[32];
#pragma unroll
    for (int i = 0; i < 32; i++) ac[i] = 0ull;

    for (int j = 0; j < 128; j++) {
        const uint64_t* kr = (const uint64_t*)(Ks + j * 64);
        uint64_t a0 = 0ull, a1 = 0ull, a2 = 0ull, a3 = 0ull;
#pragma unroll
        for (int i = 0; i < 32; i += 4) {
            a0 = fma2(q2[i],     kr[i],     a0);
            a1 = fma2(q2[i + 1], kr[i + 1], a1);
            a2 = fma2(q2[i + 2], kr[i + 2], a2);
            a3 = fma2(q2[i + 3], kr[i + 3], a3);
        }
        a0 = add2(a0, a1);
        a2 = add2(a2, a3);
        a0 = add2(a0, a2);
        float lo = __uint_as_float((uint32_t)a0);
        float hi = __uint_as_float((uint32_t)(a0 >> 32));
        float p = __expf((lo + hi) * 0.125f);
        sum += p;
        uint64_t p2 = ((uint64_t)__float_as_uint(p) << 32) | __float_as_uint(p);
        const uint64_t* vr = (const uint64_t*)(Vs + j * 64);
#pragma unroll
        for (int i = 0; i < 32; i++)
            ac[i] = fma2(p2, vr[i], ac[i]);
    }
    const float inv = 1.f / sum;
    uint32_t* op = outp + (gbase + t) * DIM + hh * 64;
#pragma unroll
    for (int i = 0; i < 16; i++) {
        float4 v;
        v.x = __uint_as_float((uint32_t)ac[2 * i])             * inv;
        v.y = __uint_as_float((uint32_t)(ac[2 * i] >> 32))     * inv;
        v.z = __uint_as_float((uint32_t)ac[2 * i + 1])         * inv;
        v.w = __uint_as_float((uint32_t)(ac[2 * i + 1] >> 32)) * inv;
        cvtstore(op + i * 4, v);
    }
}

// ---------------- launch ------------------------------------------------------
extern "C" void kernel_launch(void* const* d_in, const int* in_sizes, int n_in,
                              void* d_out, int out_size)
{
    const float* x          = (const float*)d_in[0];
    const float* edge_attr  = (const float*)d_in[1];
    const int*   edge_index = (const int*)  d_in[2];
    const float* node_w     = (const float*)d_in[4];
    const float* edge_w     = (const float*)d_in[5];
    const float* conv_w1    = (const float*)d_in[6];
    const float* conv_b1    = (const float*)d_in[7];
    const float* conv_w2    = (const float*)d_in[8];
    const float* conv_b2    = (const float*)d_in[9];
    const float* attn_in_w  = (const float*)d_in[10];
    const float* attn_in_b  = (const float*)d_in[11];
    const float* attn_out_w = (const float*)d_in[12];
    const float* attn_out_b = (const float*)d_in[13];
    const float* n1_g       = (const float*)d_in[14];
    const float* n1_b       = (const float*)d_in[15];
    const float* n2_g       = (const float*)d_in[16];
    const float* n2_b       = (const float*)d_in[17];
    const float* n3_g       = (const float*)d_in[18];
    const float* n3_b       = (const float*)d_in[19];
    const float* mlp_w1     = (const float*)d_in[20];
    const float* mlp_b1     = (const float*)d_in[21];
    const float* mlp_w2     = (const float*)d_in[22];
    const float* mlp_b2     = (const float*)d_in[23];
    float* out = (float*)d_out;

    const int* src = edge_index;
    const int* dst = edge_index + EDGES;

    float *h_, *agg_, *t2_, *t3_, *qkv_, *h1_;
    uint32_t* ebf_;
    int *deg_, *off_, *cur_;
    int2* epair_;
    uint32_t *pkx_, *pkea_, *pknw_, *pkew_, *pkw1_, *pkw2_, *pkinw_, *pkonw_,
             *pkmw1_, *pkmw2_, *pkagg_, *pkt1_, *pkh_, *pkattn_;
    cudaGetSymbolAddress((void**)&h_,    g_h);
    cudaGetSymbolAddress((void**)&ebf_,  g_ebf);
    cudaGetSymbolAddress((void**)&agg_,  g_agg);
    cudaGetSymbolAddress((void**)&t2_,   g_t2);
    cudaGetSymbolAddress((void**)&t3_,   g_t3);
    cudaGetSymbolAddress((void**)&qkv_,  g_qkv);
    cudaGetSymbolAddress((void**)&h1_,   g_h1);
    cudaGetSymbolAddress((void**)&deg_,  g_deg);
    cudaGetSymbolAddress((void**)&off_,  g_off);
    cudaGetSymbolAddress((void**)&cur_,  g_cur);
    cudaGetSymbolAddress((void**)&epair_,g_epair);
    cudaGetSymbolAddress((void**)&pkx_,   pk_x);
    cudaGetSymbolAddress((void**)&pkea_,  pk_ea);
    cudaGetSymbolAddress((void**)&pknw_,  pk_nw);
    cudaGetSymbolAddress((void**)&pkew_,  pk_ew);
    cudaGetSymbolAddress((void**)&pkw1_,  pk_w1);
    cudaGetSymbolAddress((void**)&pkw2_,  pk_w2);
    cudaGetSymbolAddress((void**)&pkinw_, pk_inw);
    cudaGetSymbolAddress((void**)&pkonw_, pk_onw);
    cudaGetSymbolAddress((void**)&pkmw1_, pk_mw1);
    cudaGetSymbolAddress((void**)&pkmw2_, pk_mw2);
    cudaGetSymbolAddress((void**)&pkagg_, pk_agg);
    cudaGetSymbolAddress((void**)&pkt1_,  pk_t1);
    cudaGetSymbolAddress((void**)&pkh_,   pk_h);
    cudaGetSymbolAddress((void**)&pkattn_,pk_attn);

    cudaFuncSetAttribute(attn_kernel, cudaFuncAttributeMaxDynamicSharedMemorySize, ATTN_SMEM);
    cudaFuncSetAttribute(gemm_tc,     cudaFuncAttributeMaxDynamicSharedMemorySize, GEMM_SMEM);

    cudaStream_t s2;
    cudaStreamCreateWithFlags(&s2, cudaStreamNonBlocking);
    cudaEvent_t evA, evB;
    cudaEventCreateWithFlags(&evA, cudaEventDisableTiming);
    cudaEventCreateWithFlags(&evB, cudaEventDisableTiming);

    // launches 0-2 = packs, launch 3 = node-embed GEMM (ncu capture window)
    pack_kernel<<<NODES * 128 / 1024, 256>>>(x, pkx_, NODES * 128 / 4);
    pack_kernel<<<32, 256>>>(node_w, pknw_, 256 * 128 / 4);
    pack_kernel<<<16, 256>>>(edge_w, pkew_, 256 * 64 / 4);
    gemm_tc<<<dim3(2, NODES / 128), 256, GEMM_SMEM>>>(pkx_, pknw_, nullptr, h_, pkh_, nullptr, NODES, 256, 128, 0);

    pack_kernel<<<(int)((size_t)EDGES * 64 / 1024), 256>>>(edge_attr, pkea_, EDGES * 64 / 4);
    // edge embed -> bf16 e
    gemm_tc<<<dim3(2, EDGES / 128), 256, GEMM_SMEM>>>(pkea_, pkew_, nullptr, nullptr, nullptr, ebf_, EDGES, 256, 64, 0);

    pack_kernel<<<NLAYERS * 256 * 256 / 1024, 256>>>(conv_w1, pkw1_, NLAYERS * 256 * 256 / 4);
    pack_kernel<<<NLAYERS * 256 * 256 / 1024, 256>>>(conv_w2, pkw2_, NLAYERS * 256 * 256 / 4);
    pack_kernel<<<NLAYERS * 768 * 256 / 1024, 256>>>(attn_in_w, pkinw_, NLAYERS * 768 * 256 / 4);
    pack_kernel<<<NLAYERS * 256 * 256 / 1024, 256>>>(attn_out_w, pkonw_, NLAYERS * 256 * 256 / 4);
    pack_kernel<<<NLAYERS * 512 * 256 / 1024, 256>>>(mlp_w1, pkmw1_, NLAYERS * 512 * 256 / 4);
    pack_kernel<<<NLAYERS * 256 * 512 / 1024, 256>>>(mlp_w2, pkmw2_, NLAYERS * 256 * 512 / 4);

    // CSR build
    cudaMemsetAsync(deg_, 0, NODES * sizeof(int));
    cudaMemsetAsync(cur_, 0, NODES * sizeof(int));
    count_deg_kernel<<<EDGES / 256, 256>>>(dst, deg_);
    scan_kernel<<<1, 1024>>>(deg_, off_);
    fill_kernel<<<EDGES / 256, 256>>>(src, dst, off_, cur_, epair_);

    for (int l = 0; l < NLAYERS; l++) {
        const uint32_t* w1  = pkw1_  + (size_t)l * 256 * 256;
        const uint32_t* w2  = pkw2_  + (size_t)l * 256 * 256;
        const uint32_t* inw = pkinw_ + (size_t)l * 768 * 256;
        const uint32_t* onw = pkonw_ + (size_t)l * 256 * 256;
        const uint32_t* mw1 = pkmw1_ + (size_t)l * 512 * 256;
        const uint32_t* mw2 = pkmw2_ + (size_t)l * 256 * 512;
        const float* b1  = conv_b1    + (size_t)l * DIM;
        const float* b2  = conv_b2    + (size_t)l * DIM;
        const float* inb = attn_in_b  + (size_t)l * 768;
        const float* onb = attn_out_b + (size_t)l * DIM;
        const float* mb1 = mlp_b1     + (size_t)l * 512;
        const float* mb2 = mlp_b2     + (size_t)l * DIM;

        // fork: attention chain on s2
        cudaEventRecord(evA, 0);
        cudaStreamWaitEvent(s2, evA, 0);
        gemm_tc<<<dim3(6, 128), 256, GEMM_SMEM, s2>>>(pkh_, inw, inb, qkv_, nullptr, nullptr, NODES, 768, 256, 0);
        attn_kernel<<<NGRAPH * 4, 128, ATTN_SMEM, s2>>>(qkv_, pkattn_);
        gemm_tc<<<dim3(2, 128), 256, GEMM_SMEM, s2>>>(pkattn_, onw, onb, t3_, nullptr, nullptr, NODES, 256, 256, 0);
        cudaEventRecord(evB, s2);

        // local chain on default stream
        gine_gather_kernel<<<NODES / 8, 256>>>(h_, ebf_, epair_, off_, pkagg_);
        gemm_tc<<<dim3(2, 128), 256, GEMM_SMEM>>>(pkagg_, w1, b1, nullptr, pkt1_, nullptr, NODES, 256, 256, 1);
        gemm_tc<<<dim3(2, 128), 256, GEMM_SMEM>>>(pkt1_,  w2, b2, t2_, nullptr, nullptr, NODES, 256, 256, 0);
        gln_kernel<<<NGRAPH, 256>>>(t2_, h_, nullptr, n1_g + l * DIM, n1_b + l * DIM,
                                    h1_, nullptr, nullptr);

        // join
        cudaStreamWaitEvent(0, evB, 0);
        gln_kernel<<<NGRAPH, 256>>>(t3_, h_, h1_, n2_g + l * DIM, n2_b + l * DIM,
                                    agg_, pkagg_, nullptr);
        gemm_tc<<<dim3(4, 128), 256, GEMM_SMEM>>>(pkagg_, mw1, mb1, nullptr, pkt1_, nullptr, NODES, 512, 256, 2);
        gemm_tc<<<dim3(2, 128), 256, GEMM_SMEM>>>(pkt1_,  mw2, mb2, t2_, nullptr, nullptr, NODES, 256, 512, 0);
        if (l == NLAYERS - 1) {
            gln_kernel<<<NGRAPH, 256>>>(t2_, agg_, nullptr, n3_g + l * DIM, n3_b + l * DIM,
                                        out, nullptr, out + (size_t)NODES * DIM);
        } else {
            gln_kernel<<<NGRAPH, 256>>>(t2_, agg_, nullptr, n3_g + l * DIM, n3_b + l * DIM,
                                        h_, pkh_, nullptr);
        }
    }
}